// round 4
// baseline (speedup 1.0000x reference)
#include <cuda_runtime.h>
#include <cuda_bf16.h>
#include <cstdint>
#include <math.h>

// ---------------------------------------------------------------- constants
#define BB   2
#define SS   2048
#define HIDD 2048
#define NH   32
#define NKV  8
#define DH   64
#define MROWS (BB*SS)        // 4096
#define KVDIM (NKV*DH)       // 512
#define KDIM  2048

// ---------------------------------------------------------------- scratch
__device__ float g_q [(size_t)MROWS * HIDD];
__device__ float g_k [(size_t)MROWS * KVDIM];
__device__ float g_v [(size_t)MROWS * KVDIM];
__device__ float g_at[(size_t)MROWS * HIDD];

__device__ __nv_bfloat16 g_hs_hi[(size_t)MROWS * KDIM];
__device__ __nv_bfloat16 g_hs_lo[(size_t)MROWS * KDIM];
__device__ __nv_bfloat16 g_wq_hi[(size_t)HIDD  * KDIM];
__device__ __nv_bfloat16 g_wq_lo[(size_t)HIDD  * KDIM];
__device__ __nv_bfloat16 g_wk_hi[(size_t)KVDIM * KDIM];
__device__ __nv_bfloat16 g_wk_lo[(size_t)KVDIM * KDIM];
__device__ __nv_bfloat16 g_wv_hi[(size_t)KVDIM * KDIM];
__device__ __nv_bfloat16 g_wv_lo[(size_t)KVDIM * KDIM];
__device__ __nv_bfloat16 g_wo_hi[(size_t)HIDD  * KDIM];
__device__ __nv_bfloat16 g_wo_lo[(size_t)HIDD  * KDIM];
__device__ __nv_bfloat16 g_at_hi[(size_t)MROWS * KDIM];
__device__ __nv_bfloat16 g_at_lo[(size_t)MROWS * KDIM];

// ---------------------------------------------------------------- helpers
__device__ __forceinline__ uint32_t smem_u32(const void* p) {
    uint32_t a;
    asm("{ .reg .u64 t; cvta.to.shared.u64 t, %1; cvt.u32.u64 %0, t; }" : "=r"(a) : "l"(p));
    return a;
}
__device__ __forceinline__ void cpa16(uint32_t s, const void* g) {
    asm volatile("cp.async.cg.shared.global [%0], [%1], 16;" :: "r"(s), "l"(g));
}
__device__ __forceinline__ void cpa_commit() {
    asm volatile("cp.async.commit_group;" ::: "memory");
}
template<int N> __device__ __forceinline__ void cpa_wait() {
    asm volatile("cp.async.wait_group %0;" :: "n"(N) : "memory");
}
__device__ __forceinline__ void ldsm_x4(uint32_t& r0, uint32_t& r1, uint32_t& r2, uint32_t& r3,
                                        uint32_t addr) {
    asm volatile("ldmatrix.sync.aligned.m8n8.x4.shared.b16 {%0,%1,%2,%3}, [%4];"
                 : "=r"(r0), "=r"(r1), "=r"(r2), "=r"(r3) : "r"(addr));
}
__device__ __forceinline__ void mma_bf16(float& c0, float& c1, float& c2, float& c3,
                                         uint32_t a0, uint32_t a1, uint32_t a2, uint32_t a3,
                                         uint32_t b0, uint32_t b1) {
    asm volatile(
        "mma.sync.aligned.m16n8k16.row.col.f32.bf16.bf16.f32 "
        "{%0,%1,%2,%3}, {%4,%5,%6,%7}, {%8,%9}, {%0,%1,%2,%3};"
        : "+f"(c0), "+f"(c1), "+f"(c2), "+f"(c3)
        : "r"(a0), "r"(a1), "r"(a2), "r"(a3), "r"(b0), "r"(b1));
}

// ---------------------------------------------------------------- split hi/lo
__global__ void split_kernel(const float* __restrict__ s,
                             __nv_bfloat16* __restrict__ hi,
                             __nv_bfloat16* __restrict__ lo, int n) {
    int i = blockIdx.x * blockDim.x + threadIdx.x;
    if (i < n) {
        float x = s[i];
        __nv_bfloat16 h = __float2bfloat16(x);
        hi[i] = h;
        lo[i] = __float2bfloat16(x - __bfloat162float(h));
    }
}

// ---------------------------------------------------------------- GEMM
// C[M,N] = (Ahi+Alo)[M,K] * (Bhi+Blo)[N,K]^T, 3-term split (hh+hl+lh).
// 128x128 CTA tile, BK=64, 8 warps (warp tile 32x64), 2-stage cp.async.
#define BK     64
#define NKIT   (KDIM / BK)         // 32
#define SROWB  144                 // 128B data + 16B pad per row
#define TILE_B (128 * SROWB)       // 18432
#define STAGE_B (4 * TILE_B)       // Ahi Alo Bhi Blo = 73728
#define GSMEM  (2 * STAGE_B)       // 147456

__global__ __launch_bounds__(256, 1) void gemm_bf16(
    const __nv_bfloat16* __restrict__ Ahi, const __nv_bfloat16* __restrict__ Alo,
    const __nv_bfloat16* __restrict__ Bhi, const __nv_bfloat16* __restrict__ Blo,
    float* __restrict__ C, int N)
{
    extern __shared__ __align__(128) char smem[];
    const uint32_t sb = smem_u32(smem);
    const int tid  = threadIdx.x;
    const int lane = tid & 31;
    const int wid  = tid >> 5;
    const int wm   = wid & 3;
    const int wn   = wid >> 2;
    const int bm = blockIdx.y * 128, bn = blockIdx.x * 128;

    // loader: threads 0-127 -> A rows, 128-255 -> B rows; one full 128B row each
    const int lr = tid & 127;
    const bool isB = tid >= 128;
    const __nv_bfloat16* ghi = isB ? Bhi + (size_t)(bn + lr) * KDIM
                                   : Ahi + (size_t)(bm + lr) * KDIM;
    const __nv_bfloat16* glo = isB ? Blo + (size_t)(bn + lr) * KDIM
                                   : Alo + (size_t)(bm + lr) * KDIM;
    const uint32_t shi = sb + (isB ? 2 * TILE_B : 0) + lr * SROWB;

    float acc[2][8][4];
#pragma unroll
    for (int i = 0; i < 2; i++)
#pragma unroll
        for (int j = 0; j < 8; j++)
#pragma unroll
            for (int r = 0; r < 4; r++) acc[i][j][r] = 0.f;

    const int a_row = wm * 32 + (lane & 15);
    const int a_kb  = (lane >> 4) * 16;
    const int b_row = wn * 64 + ((lane >> 4) << 3) + (lane & 7);
    const int b_kb  = ((lane >> 3) & 1) * 16;

    // prologue: stage 0 (k0 = 0)
#pragma unroll
    for (int c = 0; c < 8; c++) {
        cpa16(shi + c * 16,          ghi + c * 8);
        cpa16(shi + TILE_B + c * 16, glo + c * 8);
    }
    cpa_commit();

    for (int kt = 0; kt < NKIT; kt++) {
        cpa_wait<0>();
        __syncthreads();

        if (kt + 1 < NKIT) {
            const uint32_t sd = shi + ((kt + 1) & 1) * STAGE_B;
            const int k0 = (kt + 1) * BK;
#pragma unroll
            for (int c = 0; c < 8; c++) {
                cpa16(sd + c * 16,          ghi + k0 + c * 8);
                cpa16(sd + TILE_B + c * 16, glo + k0 + c * 8);
            }
            cpa_commit();
        }

        const uint32_t sA = sb + (kt & 1) * STAGE_B;
        const uint32_t sB = sA + 2 * TILE_B;

#pragma unroll
        for (int kh = 0; kh < 4; kh++) {          // four k16 steps per BK=64
            const int kbyte = kh * 32;
            uint32_t ah[2][4], al[2][4];
#pragma unroll
            for (int mt = 0; mt < 2; mt++) {
                uint32_t ra = sA + (a_row + mt * 16) * SROWB + kbyte + a_kb;
                ldsm_x4(ah[mt][0], ah[mt][1], ah[mt][2], ah[mt][3], ra);
                ldsm_x4(al[mt][0], al[mt][1], al[mt][2], al[mt][3], ra + TILE_B);
            }
            uint32_t bh[4][4], bl[4][4];
#pragma unroll
            for (int nt = 0; nt < 4; nt++) {
                uint32_t rb = sB + (b_row + nt * 16) * SROWB + kbyte + b_kb;
                ldsm_x4(bh[nt][0], bh[nt][1], bh[nt][2], bh[nt][3], rb);
                ldsm_x4(bl[nt][0], bl[nt][1], bl[nt][2], bl[nt][3], rb + TILE_B);
            }
#pragma unroll
            for (int mt = 0; mt < 2; mt++)
#pragma unroll
                for (int j = 0; j < 8; j++) {
                    const int nt = j >> 1, rb0 = (j & 1) * 2;
                    mma_bf16(acc[mt][j][0], acc[mt][j][1], acc[mt][j][2], acc[mt][j][3],
                             ah[mt][0], ah[mt][1], ah[mt][2], ah[mt][3],
                             bh[nt][rb0], bh[nt][rb0 + 1]);
                    mma_bf16(acc[mt][j][0], acc[mt][j][1], acc[mt][j][2], acc[mt][j][3],
                             ah[mt][0], ah[mt][1], ah[mt][2], ah[mt][3],
                             bl[nt][rb0], bl[nt][rb0 + 1]);
                    mma_bf16(acc[mt][j][0], acc[mt][j][1], acc[mt][j][2], acc[mt][j][3],
                             al[mt][0], al[mt][1], al[mt][2], al[mt][3],
                             bh[nt][rb0], bh[nt][rb0 + 1]);
                }
        }
        __syncthreads();
    }

#pragma unroll
    for (int mt = 0; mt < 2; mt++) {
        int m0 = bm + wm * 32 + mt * 16 + (lane >> 2);
#pragma unroll
        for (int j = 0; j < 8; j++) {
            int n0 = bn + wn * 64 + j * 8 + (lane & 3) * 2;
            float2 v0 = { acc[mt][j][0], acc[mt][j][1] };
            float2 v1 = { acc[mt][j][2], acc[mt][j][3] };
            *(float2*)(C + (size_t)m0 * N + n0)       = v0;
            *(float2*)(C + (size_t)(m0 + 8) * N + n0) = v1;
        }
    }
}

// ---------------------------------------------------------------- RoPE
__global__ void rope_kernel(float* __restrict__ q, float* __restrict__ k,
                            const float* __restrict__ cs, const float* __restrict__ sn)
{
    const int QP = MROWS * NH  * (DH / 2);
    const int KP = MROWS * NKV * (DH / 2);
    int idx = blockIdx.x * blockDim.x + threadIdx.x;
    if (idx < QP) {
        int d = idx & 31;
        int h = (idx >> 5) & (NH - 1);
        int r = idx >> 10;
        float c = cs[r * DH + d], s = sn[r * DH + d];
        float* p = q + (size_t)r * HIDD + h * DH + d;
        float x1 = p[0], x2 = p[32];
        p[0]  = x1 * c - x2 * s;
        p[32] = x2 * c + x1 * s;
    } else if (idx < QP + KP) {
        int j = idx - QP;
        int d = j & 31;
        int h = (j >> 5) & (NKV - 1);
        int r = j >> 8;
        float c = cs[r * DH + d], s = sn[r * DH + d];
        float* p = k + (size_t)r * KVDIM + h * DH + d;
        float x1 = p[0], x2 = p[32];
        p[0]  = x1 * c - x2 * s;
        p[32] = x2 * c + x1 * s;
    }
}

// ---------------------------------------------------------------- attention (fp32 SIMT)
#define AQ 128
#define AK 32
#define KPAD 68

__global__ __launch_bounds__(128) void attn_kernel(
    const float* __restrict__ Q, const float* __restrict__ Kg,
    const float* __restrict__ Vg, float* __restrict__ O)
{
    __shared__ float Ks[AK][KPAD];
    __shared__ float Vs[AK][KPAD];

    const int tid = threadIdx.x;
    const int b   = blockIdx.y >> 5;
    const int h   = blockIdx.y & 31;
    const int kvh = h >> 2;
    const int qrow = blockIdx.x * AQ + tid;

    const float scale = 0.125f;
    const float* qp = Q + ((size_t)(b * SS + qrow)) * HIDD + h * DH;

    float q[DH], o[DH];
#pragma unroll
    for (int i = 0; i < DH / 4; i++) {
        float4 v = *(const float4*)(qp + 4 * i);
        q[4*i+0] = v.x * scale; q[4*i+1] = v.y * scale;
        q[4*i+2] = v.z * scale; q[4*i+3] = v.w * scale;
        o[4*i+0] = 0.f; o[4*i+1] = 0.f; o[4*i+2] = 0.f; o[4*i+3] = 0.f;
    }

    float m = -1e30f, l = 0.f;
    const int nt = (blockIdx.x * AQ + AQ) / AK;

    const int lj   = tid >> 2;
    const int loff = (tid & 3) << 2;

    for (int t = 0; t < nt; t++) {
        const int k0 = t * AK;
        __syncthreads();
        {
            const float* kp = Kg + ((size_t)(b * SS + k0 + lj)) * KVDIM + kvh * DH;
            const float* vp = Vg + ((size_t)(b * SS + k0 + lj)) * KVDIM + kvh * DH;
#pragma unroll
            for (int i = 0; i < 4; i++) {
                int c = loff + 16 * i;
                *(float4*)&Ks[lj][c] = *(const float4*)(kp + c);
                *(float4*)&Vs[lj][c] = *(const float4*)(vp + c);
            }
        }
        __syncthreads();

        float s[AK];
        float tmax = -1e30f;
#pragma unroll
        for (int j = 0; j < AK; j++) {
            float acc = 0.f;
#pragma unroll
            for (int d = 0; d < DH / 4; d++) {
                float4 kv = *(const float4*)&Ks[j][4 * d];
                acc = fmaf(q[4*d+0], kv.x, acc);
                acc = fmaf(q[4*d+1], kv.y, acc);
                acc = fmaf(q[4*d+2], kv.z, acc);
                acc = fmaf(q[4*d+3], kv.w, acc);
            }
            acc = (k0 + j <= qrow) ? acc : -1e30f;
            s[j] = acc;
            tmax = fmaxf(tmax, acc);
        }

        if (tmax > m) {
            float mn = tmax;
            float corr = __expf(m - mn);
            m = mn;
            l *= corr;
#pragma unroll
            for (int d = 0; d < DH; d++) o[d] *= corr;
        }

#pragma unroll
        for (int j = 0; j < AK; j++) {
            float p = __expf(s[j] - m);
            l += p;
#pragma unroll
            for (int d = 0; d < DH / 4; d++) {
                float4 vv = *(const float4*)&Vs[j][4 * d];
                o[4*d+0] = fmaf(p, vv.x, o[4*d+0]);
                o[4*d+1] = fmaf(p, vv.y, o[4*d+1]);
                o[4*d+2] = fmaf(p, vv.z, o[4*d+2]);
                o[4*d+3] = fmaf(p, vv.w, o[4*d+3]);
            }
        }
    }

    const float inv = 1.f / l;
    float* op = O + ((size_t)(b * SS + qrow)) * HIDD + h * DH;
#pragma unroll
    for (int d = 0; d < DH / 4; d++) {
        float4 v = {o[4*d+0] * inv, o[4*d+1] * inv, o[4*d+2] * inv, o[4*d+3] * inv};
        *(float4*)(op + 4 * d) = v;
    }
}

// ---------------------------------------------------------------- launch
extern "C" void kernel_launch(void* const* d_in, const int* in_sizes, int n_in,
                              void* d_out, int out_size)
{
    const float* hs = (const float*)d_in[0];
    const float* cs = (const float*)d_in[1];
    const float* sn = (const float*)d_in[2];
    const float* Wq = (const float*)d_in[4];
    const float* Wk = (const float*)d_in[5];
    const float* Wv = (const float*)d_in[6];
    const float* Wo = (const float*)d_in[7];
    float* out = (float*)d_out;

    float *q, *k, *v, *at;
    cudaGetSymbolAddress((void**)&q,  g_q);
    cudaGetSymbolAddress((void**)&k,  g_k);
    cudaGetSymbolAddress((void**)&v,  g_v);
    cudaGetSymbolAddress((void**)&at, g_at);
    __nv_bfloat16 *hsh, *hsl, *wqh, *wql, *wkh, *wkl, *wvh, *wvl, *woh, *wol, *ath, *atl;
    cudaGetSymbolAddress((void**)&hsh, g_hs_hi); cudaGetSymbolAddress((void**)&hsl, g_hs_lo);
    cudaGetSymbolAddress((void**)&wqh, g_wq_hi); cudaGetSymbolAddress((void**)&wql, g_wq_lo);
    cudaGetSymbolAddress((void**)&wkh, g_wk_hi); cudaGetSymbolAddress((void**)&wkl, g_wk_lo);
    cudaGetSymbolAddress((void**)&wvh, g_wv_hi); cudaGetSymbolAddress((void**)&wvl, g_wv_lo);
    cudaGetSymbolAddress((void**)&woh, g_wo_hi); cudaGetSymbolAddress((void**)&wol, g_wo_lo);
    cudaGetSymbolAddress((void**)&ath, g_at_hi); cudaGetSymbolAddress((void**)&atl, g_at_lo);

    cudaFuncSetAttribute(gemm_bf16, cudaFuncAttributeMaxDynamicSharedMemorySize, GSMEM);

    const int nHS = MROWS * KDIM, nWQ = HIDD * KDIM, nWK = KVDIM * KDIM;
    split_kernel<<<(nHS + 255) / 256, 256>>>(hs, hsh, hsl, nHS);
    split_kernel<<<(nWQ + 255) / 256, 256>>>(Wq, wqh, wql, nWQ);
    split_kernel<<<(nWK + 255) / 256, 256>>>(Wk, wkh, wkl, nWK);
    split_kernel<<<(nWK + 255) / 256, 256>>>(Wv, wvh, wvl, nWK);
    split_kernel<<<(nWQ + 255) / 256, 256>>>(Wo, woh, wol, nWQ);

    gemm_bf16<<<dim3(HIDD / 128,  MROWS / 128), 256, GSMEM>>>(hsh, hsl, wqh, wql, q, HIDD);
    gemm_bf16<<<dim3(KVDIM / 128, MROWS / 128), 256, GSMEM>>>(hsh, hsl, wkh, wkl, k, KVDIM);
    gemm_bf16<<<dim3(KVDIM / 128, MROWS / 128), 256, GSMEM>>>(hsh, hsl, wvh, wvl, v, KVDIM);

    const int pairs = MROWS * NH * (DH / 2) + MROWS * NKV * (DH / 2);
    rope_kernel<<<pairs / 256, 256>>>(q, k, cs, sn);

    attn_kernel<<<dim3(SS / AQ, BB * NH), dim3(128)>>>(q, k, v, at);

    split_kernel<<<(nHS + 255) / 256, 256>>>(at, ath, atl, nHS);
    gemm_bf16<<<dim3(HIDD / 128, MROWS / 128), 256, GSMEM>>>(ath, atl, woh, wol, out, HIDD);
}